// round 5
// baseline (speedup 1.0000x reference)
#include <cuda_runtime.h>
#include <math.h>

// Problem dims
#define BB 32
#define SS 2048
#define II 128
#define HH 512
#define OO 128

#define RGRID 128        // persistent recurrence grid (must all be co-resident)
#define HSTRIDE 516      // 512 + 4 pad (bank-conflict-free strided rows)

// ---------------- static device scratch (no cudaMalloc allowed) ----------------
__device__ float g_Abuf[SS * BB * 1536];  // precomputed x-projections [t][b][z|r|g]
__device__ float g_H0[SS * BB * HH];      // layer-0 output sequence [t][b][h]
__device__ float g_H1[SS * BB * HH];      // layer-1 output sequence
__device__ float g_hc[2 * BB * HH];       // running hidden state per layer
__device__ float g_zbuf[BB * HH];         // z gate (cross-CTA within a step)
__device__ float g_rhbuf[BB * HH];        // r*h (cross-CTA within a step)

__device__ unsigned g_bar_cnt = 0;
__device__ unsigned g_bar_gen = 0;

// ---------------- grid-wide barrier (all RGRID CTAs co-resident) ----------------
__device__ __forceinline__ void grid_sync() {
    __threadfence();          // make this thread's global writes visible
    __syncthreads();
    if (threadIdx.x == 0) {
        unsigned gen = *(volatile unsigned*)&g_bar_gen;
        if (atomicAdd(&g_bar_cnt, 1u) == RGRID - 1) {
            g_bar_cnt = 0;
            __threadfence();
            *(volatile unsigned*)&g_bar_gen = gen + 1;
        } else {
            while (*(volatile unsigned*)&g_bar_gen == gen) { __nanosleep(32); }
        }
        __threadfence();
    }
    __syncthreads();
}

// ---------------- SGEMM: C[r][n] = sum_k Arow(r)[k] * W[k][n] + bias[n] ----------------
// amode 0: Arow(r) = A + (r%32)*S*I + (r/32)*I   (gather from x, K=128)
// amode 1: Arow(r) = A + r*K                      (dense [t][b] layout)
// N is split into gates of width ngate; W0g/W1g/W2g are the per-gate weight mats.
// omode 0: C[r*ldc + n]
// omode 1: C[(r%32)*S*OO + (r/32)*OO + n]         (write (B,S,O) row-major)
__global__ __launch_bounds__(256, 2) void sgemm_kernel(
    const float* __restrict__ A, int amode, int K,
    const float* __restrict__ W0g, const float* __restrict__ W1g, const float* __restrict__ W2g,
    const float* __restrict__ b0g, const float* __restrict__ b1g, const float* __restrict__ b2g,
    int ngate, float* __restrict__ C, int omode, int ldc)
{
    __shared__ float As[8][128];
    __shared__ float Bs[8][132];

    const int tid = threadIdx.x;
    const int bm = blockIdx.x;
    const int ncol0 = blockIdx.y * 128;      // each 128-block lives inside one gate
    const int gate = ncol0 / ngate;
    const float* W    = (gate == 0) ? W0g : (gate == 1) ? W1g : W2g;
    const float* bias = (gate == 0) ? b0g : (gate == 1) ? b1g : b2g;
    const int ng_off = ncol0 - gate * ngate;

    const int tx = tid & 15;
    const int ty = tid >> 4;

    float acc[8][8];
#pragma unroll
    for (int i = 0; i < 8; i++)
#pragma unroll
        for (int j = 0; j < 8; j++) acc[i][j] = 0.f;

    const int arow = tid >> 1;        // 0..127
    const int ak = (tid & 1) * 4;     // 0 or 4
    const int grow = bm * 128 + arow;
    long aoff;
    if (amode == 0) aoff = (long)(grow & 31) * (SS * II) + (long)(grow >> 5) * II;
    else            aoff = (long)grow * K;

    const int bk = tid >> 5;          // 0..7
    const int bn = (tid & 31) * 4;    // 0..124

    for (int kk = 0; kk < K; kk += 8) {
        float4 av = *(const float4*)(A + aoff + (kk + ak));
        As[ak + 0][arow] = av.x;
        As[ak + 1][arow] = av.y;
        As[ak + 2][arow] = av.z;
        As[ak + 3][arow] = av.w;
        float4 wv = *(const float4*)(W + (long)(kk + bk) * ngate + (ng_off + bn));
        *(float4*)&Bs[bk][bn] = wv;
        __syncthreads();
#pragma unroll
        for (int k = 0; k < 8; k++) {
            float rm[8], rn[8];
            *(float4*)&rm[0] = *(const float4*)&As[k][ty * 8];
            *(float4*)&rm[4] = *(const float4*)&As[k][ty * 8 + 4];
            *(float4*)&rn[0] = *(const float4*)&Bs[k][tx * 8];
            *(float4*)&rn[4] = *(const float4*)&Bs[k][tx * 8 + 4];
#pragma unroll
            for (int i = 0; i < 8; i++)
#pragma unroll
                for (int j = 0; j < 8; j++)
                    acc[i][j] += rm[i] * rn[j];
        }
        __syncthreads();
    }

#pragma unroll
    for (int i = 0; i < 8; i++) {
        int row = bm * 128 + ty * 8 + i;
        long obase;
        if (omode == 0) obase = (long)row * ldc + ncol0;
        else            obase = (long)(row & 31) * (SS * OO) + (long)(row >> 5) * OO + ncol0;
#pragma unroll
        for (int j = 0; j < 8; j++)
            C[obase + tx * 8 + j] = acc[i][j] + bias[ng_off + tx * 8 + j];
    }
}

// ---------------- persistent GRU recurrence for one layer ----------------
// CTA i owns z/r columns [8i,8i+8) (c<512 -> z col c, else r col c-512) and
// g columns [4i,4i+4). Recurrent weight slices live in SMEM for all 2048 steps.
__global__ void __launch_bounds__(256, 1) gru_recur_kernel(
    const float* __restrict__ Abuf,
    const float* __restrict__ Whz, const float* __restrict__ Whr, const float* __restrict__ Whg,
    float* __restrict__ hcur, float* __restrict__ Hout,
    float* __restrict__ zbuf, float* __restrict__ rhbuf)
{
    extern __shared__ float smf[];
    float* Wzr_s = smf;                      // 8  x HSTRIDE
    float* Wg_s  = Wzr_s + 8 * HSTRIDE;      // 4  x HSTRIDE
    float* h_s   = Wg_s + 4 * HSTRIDE;       // 32 x HSTRIDE
    float* rh_s  = h_s + 32 * HSTRIDE;       // 32 x HSTRIDE
    float* red   = rh_s + 32 * HSTRIDE;      // 128

    const int tid = threadIdx.x;
    const int cta = blockIdx.x;
    const int zc0 = cta * 8;
    const int gc0 = cta * 4;

    // stage step-invariant weight slices into SMEM (once)
    for (int idx = tid; idx < 8 * 512; idx += 256) {
        int jc = idx >> 9, k = idx & 511;
        int c = zc0 + jc;
        Wzr_s[jc * HSTRIDE + k] = (c < 512) ? Whz[k * 512 + c] : Whr[k * 512 + c - 512];
    }
    for (int idx = tid; idx < 4 * 512; idx += 256) {
        int jc = idx >> 9, k = idx & 511;
        Wg_s[jc * HSTRIDE + k] = Whg[k * 512 + gc0 + jc];
    }

    const int a_jc = tid & 7,  a_b = tid >> 3;
    const int b_jc = tid & 3,  b_b = (tid >> 2) & 31, b_kh = tid >> 7;

    for (int t = 0; t < SS; t++) {
        // stage h (written by other CTAs last step -> bypass L1)
        for (int idx = tid; idx < 32 * 128; idx += 256) {
            float4 v = __ldcg((const float4*)hcur + idx);
            int row = idx >> 7, c4 = idx & 127;
            *(float4*)&h_s[row * HSTRIDE + c4 * 4] = v;
        }
        __syncthreads();

        // ---- Phase A: z & r pre-activations for my 8 columns ----
        {
            const int c = zc0 + a_jc;
            const float* hr = h_s + a_b * HSTRIDE;
            const float* wr = Wzr_s + a_jc * HSTRIDE;
            float s0 = Abuf[(t * 32 + a_b) * 1536 + c], s1 = 0.f, s2 = 0.f, s3 = 0.f;
#pragma unroll 16
            for (int k = 0; k < 512; k += 4) {
                float4 hv = *(const float4*)(hr + k);
                float4 wv = *(const float4*)(wr + k);
                s0 += hv.x * wv.x; s1 += hv.y * wv.y;
                s2 += hv.z * wv.z; s3 += hv.w * wv.w;
            }
            float pre = (s0 + s1) + (s2 + s3);
            float sg = 1.f / (1.f + __expf(-pre));
            if (c < 512) {
                zbuf[a_b * 512 + c] = sg;                 // z
            } else {
                int rc = c - 512;
                rhbuf[a_b * 512 + rc] = sg * h_s[a_b * HSTRIDE + rc];  // r*h
            }
        }
        grid_sync();

        // stage r*h
        for (int idx = tid; idx < 32 * 128; idx += 256) {
            float4 v = __ldcg((const float4*)rhbuf + idx);
            int row = idx >> 7, c4 = idx & 127;
            *(float4*)&rh_s[row * HSTRIDE + c4 * 4] = v;
        }
        __syncthreads();

        // ---- Phase B: g for my 4 columns (K split in halves), h update ----
        {
            const float* rr = rh_s + b_b * HSTRIDE + b_kh * 256;
            const float* wr = Wg_s + b_jc * HSTRIDE + b_kh * 256;
            float s0 = 0.f, s1 = 0.f, s2 = 0.f, s3 = 0.f;
#pragma unroll 16
            for (int k = 0; k < 256; k += 4) {
                float4 hv = *(const float4*)(rr + k);
                float4 wv = *(const float4*)(wr + k);
                s0 += hv.x * wv.x; s1 += hv.y * wv.y;
                s2 += hv.z * wv.z; s3 += hv.w * wv.w;
            }
            float part = (s0 + s1) + (s2 + s3);
            if (b_kh) red[tid - 128] = part;
            __syncthreads();
            if (!b_kh) {
                int c = gc0 + b_jc;
                float pre = Abuf[(t * 32 + b_b) * 1536 + 1024 + c] + part + red[tid];
                float g = tanhf(pre);
                float z = __ldcg(zbuf + b_b * 512 + c);
                float ho = h_s[b_b * HSTRIDE + c];
                float hn = z * ho + (1.f - z) * g;
                hcur[b_b * 512 + c] = hn;
                Hout[(t * 32 + b_b) * 512 + c] = hn;
            }
        }
        grid_sync();
    }
}

// ---------------- small helpers ----------------
__global__ void init_h_kernel(const float* __restrict__ h0, float* __restrict__ hc) {
    int i = blockIdx.x * 256 + threadIdx.x;   // 2*32*512
    if (i < 2 * BB * HH) {
        int l = i >> 14, rem = i & 16383, b = rem >> 9, h = rem & 511;
        hc[i] = h0[b * 1024 + l * 512 + h];   // h0 is (B, L, H)
    }
}

__global__ void copy_hidden_kernel(float* __restrict__ out, const float* __restrict__ hc) {
    int i = blockIdx.x * 256 + threadIdx.x;   // (B, L, H)
    if (i < BB * 2 * HH) {
        int b = i >> 10, rem = i & 1023;
        int l = rem >> 9, h = rem & 511;
        out[i] = hc[l * (BB * HH) + (b << 9) + h];
    }
}

// ---------------- launch ----------------
extern "C" void kernel_launch(void* const* d_in, const int* in_sizes, int n_in,
                              void* d_out, int out_size)
{
    const float* x    = (const float*)d_in[0];
    const float* h0   = (const float*)d_in[1];
    const float* W0xz = (const float*)d_in[2];
    const float* W0hz = (const float*)d_in[3];
    const float* b0z  = (const float*)d_in[4];
    const float* W0xr = (const float*)d_in[5];
    const float* W0hr = (const float*)d_in[6];
    const float* b0r  = (const float*)d_in[7];
    const float* W0xg = (const float*)d_in[8];
    const float* W0hg = (const float*)d_in[9];
    const float* b0g  = (const float*)d_in[10];
    const float* W1xz = (const float*)d_in[11];
    const float* W1hz = (const float*)d_in[12];
    const float* b1z  = (const float*)d_in[13];
    const float* W1xr = (const float*)d_in[14];
    const float* W1hr = (const float*)d_in[15];
    const float* b1r  = (const float*)d_in[16];
    const float* W1xg = (const float*)d_in[17];
    const float* W1hg = (const float*)d_in[18];
    const float* b1g  = (const float*)d_in[19];
    const float* Wy   = (const float*)d_in[20];
    const float* by   = (const float*)d_in[21];
    float* out = (float*)d_out;

    float *Abuf, *H0, *H1, *hc, *zb, *rhb;
    cudaGetSymbolAddress((void**)&Abuf, g_Abuf);
    cudaGetSymbolAddress((void**)&H0,   g_H0);
    cudaGetSymbolAddress((void**)&H1,   g_H1);
    cudaGetSymbolAddress((void**)&hc,   g_hc);
    cudaGetSymbolAddress((void**)&zb,   g_zbuf);
    cudaGetSymbolAddress((void**)&rhb,  g_rhbuf);

    const size_t smem = (size_t)(76 * HSTRIDE + 128) * sizeof(float); // ~157 KB
    cudaFuncSetAttribute(gru_recur_kernel,
                         cudaFuncAttributeMaxDynamicSharedMemorySize, (int)smem);

    // h init
    init_h_kernel<<<128, 256>>>(h0, hc);

    dim3 gproj(512, 12);  // M=65536/128, N=1536/128

    // layer 0: x-projection GEMM, then recurrence
    sgemm_kernel<<<gproj, 256>>>(x, 0, II, W0xz, W0xr, W0xg, b0z, b0r, b0g,
                                 512, Abuf, 0, 1536);
    gru_recur_kernel<<<RGRID, 256, smem>>>(Abuf, W0hz, W0hr, W0hg,
                                           hc, H0, zb, rhb);

    // layer 1: input-projection GEMM on layer-0 outputs, then recurrence
    sgemm_kernel<<<gproj, 256>>>(H0, 1, HH, W1xz, W1xr, W1xg, b1z, b1r, b1g,
                                 512, Abuf, 0, 1536);
    gru_recur_kernel<<<RGRID, 256, smem>>>(Abuf, W1hz, W1hr, W1hg,
                                           hc + BB * HH, H1, zb, rhb);

    // output head: Y = H1 @ Wy + by  -> (B,S,O) row-major in d_out
    dim3 ghead(512, 1);
    sgemm_kernel<<<ghead, 256>>>(H1, 1, HH, Wy, Wy, Wy, by, by, by,
                                 128, out, 1, 0);

    // hidden_state tail (B, L, H), if the harness buffer includes it
    if (out_size >= BB * SS * OO + BB * 2 * HH) {
        copy_hidden_kernel<<<128, 256>>>(out + BB * SS * OO, hc);
    }
}

// round 6
// speedup vs baseline: 1.3094x; 1.3094x over previous
#include <cuda_runtime.h>
#include <math.h>

// Problem dims
#define BB 32
#define SS 2048
#define II 128
#define HH 512
#define OO 128

#define RGRID 128        // persistent recurrence grid (must all be co-resident)
#define HSTRIDE 516      // 512 + 4 pad (bank-conflict-free strided rows)

// ---------------- static device scratch (no cudaMalloc allowed) ----------------
__device__ float g_Abuf[SS * BB * 1536];  // precomputed x-projections [t][b][z|r|g]
__device__ float g_H0[SS * BB * HH];      // layer-0 output sequence [t][b][h]
__device__ float g_H1[SS * BB * HH];      // layer-1 output sequence
__device__ float g_hc[2 * BB * HH];       // running hidden state per layer
__device__ float g_rhbuf[BB * HH];        // r*h (cross-CTA within a step)

__device__ unsigned g_bar_cnt = 0;

// ---------------- cp.async helpers ----------------
__device__ __forceinline__ void cp_async16(void* smem, const void* gmem) {
    unsigned s = (unsigned)__cvta_generic_to_shared(smem);
    asm volatile("cp.async.cg.shared.global [%0], [%1], 16;" :: "r"(s), "l"(gmem));
}
__device__ __forceinline__ void cp_commit() {
    asm volatile("cp.async.commit_group;");
}
template<int N> __device__ __forceinline__ void cp_wait() {
    asm volatile("cp.async.wait_group %0;" :: "n"(N));
}

// ---------------- grid-wide barrier (all RGRID CTAs co-resident) ----------------
// CG-style: bar.sync -> elected thread red.release + ld.acquire spin on the
// SAME counter (coherence-order transitivity) -> bar.sync. No per-thread fence.
__device__ __forceinline__ void grid_sync(unsigned& tgt) {
    __syncthreads();
    if (threadIdx.x == 0) {
        tgt += RGRID;
        asm volatile("red.release.gpu.global.add.u32 [%0], %1;"
                     :: "l"(&g_bar_cnt), "r"(1u) : "memory");
        unsigned v;
        do {
            asm volatile("ld.acquire.gpu.global.u32 %0, [%1];"
                         : "=r"(v) : "l"(&g_bar_cnt) : "memory");
        } while (v < tgt);
    }
    __syncthreads();
}

__global__ void reset_bar_kernel() { g_bar_cnt = 0; }

// ---------------- SGEMM (unchanged from R4) ----------------
__global__ __launch_bounds__(256, 2) void sgemm_kernel(
    const float* __restrict__ A, int amode, int K,
    const float* __restrict__ W0g, const float* __restrict__ W1g, const float* __restrict__ W2g,
    const float* __restrict__ b0g, const float* __restrict__ b1g, const float* __restrict__ b2g,
    int ngate, float* __restrict__ C, int omode, int ldc)
{
    __shared__ float As[8][128];
    __shared__ float Bs[8][132];

    const int tid = threadIdx.x;
    const int bm = blockIdx.x;
    const int ncol0 = blockIdx.y * 128;
    const int gate = ncol0 / ngate;
    const float* W    = (gate == 0) ? W0g : (gate == 1) ? W1g : W2g;
    const float* bias = (gate == 0) ? b0g : (gate == 1) ? b1g : b2g;
    const int ng_off = ncol0 - gate * ngate;

    const int tx = tid & 15;
    const int ty = tid >> 4;

    float acc[8][8];
#pragma unroll
    for (int i = 0; i < 8; i++)
#pragma unroll
        for (int j = 0; j < 8; j++) acc[i][j] = 0.f;

    const int arow = tid >> 1;
    const int ak = (tid & 1) * 4;
    const int grow = bm * 128 + arow;
    long aoff;
    if (amode == 0) aoff = (long)(grow & 31) * (SS * II) + (long)(grow >> 5) * II;
    else            aoff = (long)grow * K;

    const int bk = tid >> 5;
    const int bn = (tid & 31) * 4;

    for (int kk = 0; kk < K; kk += 8) {
        float4 av = *(const float4*)(A + aoff + (kk + ak));
        As[ak + 0][arow] = av.x;
        As[ak + 1][arow] = av.y;
        As[ak + 2][arow] = av.z;
        As[ak + 3][arow] = av.w;
        float4 wv = *(const float4*)(W + (long)(kk + bk) * ngate + (ng_off + bn));
        *(float4*)&Bs[bk][bn] = wv;
        __syncthreads();
#pragma unroll
        for (int k = 0; k < 8; k++) {
            float rm[8], rn[8];
            *(float4*)&rm[0] = *(const float4*)&As[k][ty * 8];
            *(float4*)&rm[4] = *(const float4*)&As[k][ty * 8 + 4];
            *(float4*)&rn[0] = *(const float4*)&Bs[k][tx * 8];
            *(float4*)&rn[4] = *(const float4*)&Bs[k][tx * 8 + 4];
#pragma unroll
            for (int i = 0; i < 8; i++)
#pragma unroll
                for (int j = 0; j < 8; j++)
                    acc[i][j] += rm[i] * rn[j];
        }
        __syncthreads();
    }

#pragma unroll
    for (int i = 0; i < 8; i++) {
        int row = bm * 128 + ty * 8 + i;
        long obase;
        if (omode == 0) obase = (long)row * ldc + ncol0;
        else            obase = (long)(row & 31) * (SS * OO) + (long)(row >> 5) * OO + ncol0;
#pragma unroll
        for (int j = 0; j < 8; j++)
            C[obase + tx * 8 + j] = acc[i][j] + bias[ng_off + tx * 8 + j];
    }
}

// ---------------- persistent GRU recurrence for one layer ----------------
// CTA i owns columns [4i, 4i+4) of z, r AND g. z stays in SMEM (same CTA does
// the h update for those columns). Recurrent weight slices (12 cols x 512)
// live in SMEM for all 2048 steps. h and r*h staged via cp.async pipelined
// against the dot-product accumulation.
template<int C, int W>
__device__ __forceinline__ void accA(const float* hr, const float* wr,
                                     float& s0, float& s1, float& s2, float& s3)
{
    cp_wait<W>();
    __syncthreads();
#pragma unroll
    for (int k = C * 128; k < C * 128 + 128; k += 4) {
        float4 hv = *(const float4*)(hr + k);
        float4 wv = *(const float4*)(wr + k);
        s0 += hv.x * wv.x; s1 += hv.y * wv.y;
        s2 += hv.z * wv.z; s3 += hv.w * wv.w;
    }
}

template<int C, int W>
__device__ __forceinline__ void accB(const float* rr, const float* wg, int kh,
                                     float& s0, float& s1, float& s2, float& s3)
{
    cp_wait<W>();
    __syncthreads();
    const int kb = kh * 256 + C * 64;
#pragma unroll
    for (int k = 0; k < 64; k += 4) {
        float4 hv = *(const float4*)(rr + kb + k);
        float4 wv = *(const float4*)(wg + kb + k);
        s0 += hv.x * wv.x; s1 += hv.y * wv.y;
        s2 += hv.z * wv.z; s3 += hv.w * wv.w;
    }
}

__global__ void __launch_bounds__(256, 1) gru_recur_kernel(
    const float* __restrict__ Abuf,
    const float* __restrict__ Whz, const float* __restrict__ Whr, const float* __restrict__ Whg,
    float* __restrict__ hcur, float* __restrict__ Hout,
    float* __restrict__ rhbuf)
{
    extern __shared__ float smf[];
    float* w_s  = smf;                    // 12 x HSTRIDE : z(0..3) r(4..7) g(8..11)
    float* h_s  = w_s + 12 * HSTRIDE;     // 32 x HSTRIDE
    float* rh_s = h_s + 32 * HSTRIDE;     // 32 x HSTRIDE
    float* z_s  = rh_s + 32 * HSTRIDE;    // 128
    float* red  = z_s + 128;              // 128

    const int tid = threadIdx.x;
    const int cta = blockIdx.x;
    const int c0 = cta * 4;

    // stage step-invariant weight slices into SMEM (once)
    for (int idx = tid; idx < 12 * 512; idx += 256) {
        int jr = idx >> 9, k = idx & 511;
        const float* Wm = (jr < 4) ? Whz : (jr < 8) ? Whr : Whg;
        w_s[jr * HSTRIDE + k] = Wm[k * 512 + c0 + (jr & 3)];
    }

    // phase A mapping: one dot per thread
    const int a_b = tid >> 3, a_j = tid & 7;
    const int a_col = c0 + (a_j & 3);
    const float* a_wr = w_s + a_j * HSTRIDE;
    const float* a_hr = h_s + a_b * HSTRIDE;

    // phase B mapping
    const int b_jc = tid & 3, b_b = (tid >> 2) & 31, b_kh = tid >> 7;
    const float* b_rr = rh_s + b_b * HSTRIDE;
    const float* b_wg = w_s + (8 + b_jc) * HSTRIDE;

    unsigned tgt = 0;

    for (int t = 0; t < SS; t++) {
        // ---- stage h: 4 commit groups of 16KB (k-chunks of 128) ----
#pragma unroll
        for (int c = 0; c < 4; c++) {
#pragma unroll
            for (int jj = 0; jj < 4; jj++) {
                int e = jj * 256 + tid;         // 0..1023
                int row = e >> 5, c4 = e & 31;
                cp_async16(&h_s[row * HSTRIDE + c * 128 + c4 * 4],
                           hcur + row * 512 + c * 128 + c4 * 4);
            }
            cp_commit();
        }

        // ---- Phase A: z & r pre-activations (pipelined with staging) ----
        float a0 = __ldg(Abuf + (size_t)(t * 32 + a_b) * 1536 +
                         ((a_j < 4) ? a_col : 512 + a_col));
        float s0 = a0, s1 = 0.f, s2 = 0.f, s3 = 0.f;
        accA<0, 3>(a_hr, a_wr, s0, s1, s2, s3);
        accA<1, 2>(a_hr, a_wr, s0, s1, s2, s3);
        accA<2, 1>(a_hr, a_wr, s0, s1, s2, s3);
        accA<3, 0>(a_hr, a_wr, s0, s1, s2, s3);
        {
            float pre = (s0 + s1) + (s2 + s3);
            float sg = 1.f / (1.f + __expf(-pre));
            if (a_j < 4) {
                z_s[a_b * 4 + a_j] = sg;
            } else {
                float rh = sg * h_s[a_b * HSTRIDE + a_col];
                __stcg(rhbuf + a_b * 512 + a_col, rh);
            }
        }
        grid_sync(tgt);

        // ---- stage r*h: 4 k-interleaved commit groups (both K-halves per group) ----
#pragma unroll
        for (int c = 0; c < 4; c++) {
#pragma unroll
            for (int jj = 0; jj < 4; jj++) {
                int e = jj * 256 + tid;         // 0..1023
                int half = e >> 9, rem = e & 511;
                int row = rem >> 4, c4 = rem & 15;
                int kf = half * 256 + c * 64 + c4 * 4;
                cp_async16(&rh_s[row * HSTRIDE + kf], rhbuf + row * 512 + kf);
            }
            cp_commit();
        }

        // ---- Phase B: g (K split in halves), h update ----
        float u0 = 0.f, u1 = 0.f, u2 = 0.f, u3 = 0.f;
        accB<0, 3>(b_rr, b_wg, b_kh, u0, u1, u2, u3);
        accB<1, 2>(b_rr, b_wg, b_kh, u0, u1, u2, u3);
        accB<2, 1>(b_rr, b_wg, b_kh, u0, u1, u2, u3);
        accB<3, 0>(b_rr, b_wg, b_kh, u0, u1, u2, u3);
        {
            float part = (u0 + u1) + (u2 + u3);
            if (b_kh) red[tid - 128] = part;
            __syncthreads();
            if (!b_kh) {
                int c = c0 + b_jc;
                float pre = __ldg(Abuf + (size_t)(t * 32 + b_b) * 1536 + 1024 + c)
                            + part + red[tid];
                float g = tanhf(pre);
                float z = z_s[b_b * 4 + b_jc];
                float ho = h_s[b_b * HSTRIDE + c];
                float hn = z * ho + (1.f - z) * g;
                __stcg(hcur + b_b * 512 + c, hn);
                Hout[(size_t)(t * 32 + b_b) * 512 + c] = hn;
            }
        }
        grid_sync(tgt);
    }
}

// ---------------- small helpers ----------------
__global__ void init_h_kernel(const float* __restrict__ h0, float* __restrict__ hc) {
    int i = blockIdx.x * 256 + threadIdx.x;
    if (i < 2 * BB * HH) {
        int l = i >> 14, rem = i & 16383, b = rem >> 9, h = rem & 511;
        hc[i] = h0[b * 1024 + l * 512 + h];
    }
}

__global__ void copy_hidden_kernel(float* __restrict__ out, const float* __restrict__ hc) {
    int i = blockIdx.x * 256 + threadIdx.x;
    if (i < BB * 2 * HH) {
        int b = i >> 10, rem = i & 1023;
        int l = rem >> 9, h = rem & 511;
        out[i] = hc[l * (BB * HH) + (b << 9) + h];
    }
}

// ---------------- launch ----------------
extern "C" void kernel_launch(void* const* d_in, const int* in_sizes, int n_in,
                              void* d_out, int out_size)
{
    const float* x    = (const float*)d_in[0];
    const float* h0   = (const float*)d_in[1];
    const float* W0xz = (const float*)d_in[2];
    const float* W0hz = (const float*)d_in[3];
    const float* b0z  = (const float*)d_in[4];
    const float* W0xr = (const float*)d_in[5];
    const float* W0hr = (const float*)d_in[6];
    const float* b0r  = (const float*)d_in[7];
    const float* W0xg = (const float*)d_in[8];
    const float* W0hg = (const float*)d_in[9];
    const float* b0g  = (const float*)d_in[10];
    const float* W1xz = (const float*)d_in[11];
    const float* W1hz = (const float*)d_in[12];
    const float* b1z  = (const float*)d_in[13];
    const float* W1xr = (const float*)d_in[14];
    const float* W1hr = (const float*)d_in[15];
    const float* b1r  = (const float*)d_in[16];
    const float* W1xg = (const float*)d_in[17];
    const float* W1hg = (const float*)d_in[18];
    const float* b1g  = (const float*)d_in[19];
    const float* Wy   = (const float*)d_in[20];
    const float* by   = (const float*)d_in[21];
    float* out = (float*)d_out;

    float *Abuf, *H0, *H1, *hc, *rhb;
    cudaGetSymbolAddress((void**)&Abuf, g_Abuf);
    cudaGetSymbolAddress((void**)&H0,   g_H0);
    cudaGetSymbolAddress((void**)&H1,   g_H1);
    cudaGetSymbolAddress((void**)&hc,   g_hc);
    cudaGetSymbolAddress((void**)&rhb,  g_rhbuf);

    const size_t smem = (size_t)(76 * HSTRIDE + 256) * sizeof(float); // ~158 KB
    cudaFuncSetAttribute(gru_recur_kernel,
                         cudaFuncAttributeMaxDynamicSharedMemorySize, (int)smem);

    init_h_kernel<<<128, 256>>>(h0, hc);

    dim3 gproj(512, 12);  // M=65536/128, N=1536/128

    // layer 0
    sgemm_kernel<<<gproj, 256>>>(x, 0, II, W0xz, W0xr, W0xg, b0z, b0r, b0g,
                                 512, Abuf, 0, 1536);
    reset_bar_kernel<<<1, 1>>>();
    gru_recur_kernel<<<RGRID, 256, smem>>>(Abuf, W0hz, W0hr, W0hg,
                                           hc, H0, rhb);

    // layer 1
    sgemm_kernel<<<gproj, 256>>>(H0, 1, HH, W1xz, W1xr, W1xg, b1z, b1r, b1g,
                                 512, Abuf, 0, 1536);
    reset_bar_kernel<<<1, 1>>>();
    gru_recur_kernel<<<RGRID, 256, smem>>>(Abuf, W1hz, W1hr, W1hg,
                                           hc + BB * HH, H1, rhb);

    // output head
    dim3 ghead(512, 1);
    sgemm_kernel<<<ghead, 256>>>(H1, 1, HH, Wy, Wy, Wy, by, by, by,
                                 128, out, 1, 0);

    if (out_size >= BB * SS * OO + BB * 2 * HH) {
        copy_hidden_kernel<<<128, 256>>>(out + BB * SS * OO, hc);
    }
}

// round 8
// speedup vs baseline: 1.5124x; 1.1551x over previous
#include <cuda_runtime.h>
#include <math.h>

// Problem dims
#define BB 32
#define SS 2048
#define II 128
#define HH 512
#define OO 128

#define RGRID 128        // persistent recurrence grid (must all be co-resident)
#define HSTRIDE 516      // 512 + 4 pad (conflict-free lane-b strided rows)

// ---------------- static device scratch ----------------
__device__ float g_Abuf[SS * BB * 1536];  // x-projections [t][b][z|r|g]
__device__ float g_H0[SS * BB * HH];
__device__ float g_H1[SS * BB * HH];
__device__ float g_hc[2 * BB * HH];
__device__ float g_rhbuf[BB * HH];

__device__ unsigned g_bar_cnt = 0;

// ---------------- cp.async helpers ----------------
__device__ __forceinline__ void cp_async16(void* smem, const void* gmem) {
    unsigned s = (unsigned)__cvta_generic_to_shared(smem);
    asm volatile("cp.async.cg.shared.global [%0], [%1], 16;" :: "r"(s), "l"(gmem));
}
__device__ __forceinline__ void cp_commit() {
    asm volatile("cp.async.commit_group;");
}
template<int N> __device__ __forceinline__ void cp_wait() {
    asm volatile("cp.async.wait_group %0;" :: "n"(N));
}

// ---------------- grid-wide barrier ----------------
__device__ __forceinline__ void grid_sync(unsigned& tgt) {
    __syncthreads();
    if (threadIdx.x == 0) {
        tgt += RGRID;
        asm volatile("red.release.gpu.global.add.u32 [%0], %1;"
                     :: "l"(&g_bar_cnt), "r"(1u) : "memory");
        unsigned v;
        do {
            asm volatile("ld.acquire.gpu.global.u32 %0, [%1];"
                         : "=r"(v) : "l"(&g_bar_cnt) : "memory");
        } while (v < tgt);
    }
    __syncthreads();
}

__global__ void reset_bar_kernel() { g_bar_cnt = 0; }

// ---------------- SGEMM (unchanged, known-good) ----------------
__global__ __launch_bounds__(256, 2) void sgemm_kernel(
    const float* __restrict__ A, int amode, int K,
    const float* __restrict__ W0g, const float* __restrict__ W1g, const float* __restrict__ W2g,
    const float* __restrict__ b0g, const float* __restrict__ b1g, const float* __restrict__ b2g,
    int ngate, float* __restrict__ C, int omode, int ldc)
{
    __shared__ float As[8][128];
    __shared__ float Bs[8][132];

    const int tid = threadIdx.x;
    const int bm = blockIdx.x;
    const int ncol0 = blockIdx.y * 128;
    const int gate = ncol0 / ngate;
    const float* W    = (gate == 0) ? W0g : (gate == 1) ? W1g : W2g;
    const float* bias = (gate == 0) ? b0g : (gate == 1) ? b1g : b2g;
    const int ng_off = ncol0 - gate * ngate;

    const int tx = tid & 15;
    const int ty = tid >> 4;

    float acc[8][8];
#pragma unroll
    for (int i = 0; i < 8; i++)
#pragma unroll
        for (int j = 0; j < 8; j++) acc[i][j] = 0.f;

    const int arow = tid >> 1;
    const int ak = (tid & 1) * 4;
    const int grow = bm * 128 + arow;
    long aoff;
    if (amode == 0) aoff = (long)(grow & 31) * (SS * II) + (long)(grow >> 5) * II;
    else            aoff = (long)grow * K;

    const int bk = tid >> 5;
    const int bn = (tid & 31) * 4;

    for (int kk = 0; kk < K; kk += 8) {
        float4 av = *(const float4*)(A + aoff + (kk + ak));
        As[ak + 0][arow] = av.x;
        As[ak + 1][arow] = av.y;
        As[ak + 2][arow] = av.z;
        As[ak + 3][arow] = av.w;
        float4 wv = *(const float4*)(W + (long)(kk + bk) * ngate + (ng_off + bn));
        *(float4*)&Bs[bk][bn] = wv;
        __syncthreads();
#pragma unroll
        for (int k = 0; k < 8; k++) {
            float rm[8], rn[8];
            *(float4*)&rm[0] = *(const float4*)&As[k][ty * 8];
            *(float4*)&rm[4] = *(const float4*)&As[k][ty * 8 + 4];
            *(float4*)&rn[0] = *(const float4*)&Bs[k][tx * 8];
            *(float4*)&rn[4] = *(const float4*)&Bs[k][tx * 8 + 4];
#pragma unroll
            for (int i = 0; i < 8; i++)
#pragma unroll
                for (int j = 0; j < 8; j++)
                    acc[i][j] += rm[i] * rn[j];
        }
        __syncthreads();
    }

#pragma unroll
    for (int i = 0; i < 8; i++) {
        int row = bm * 128 + ty * 8 + i;
        long obase;
        if (omode == 0) obase = (long)row * ldc + ncol0;
        else            obase = (long)(row & 31) * (SS * OO) + (long)(row >> 5) * OO + ncol0;
#pragma unroll
        for (int j = 0; j < 8; j++)
            C[obase + tx * 8 + j] = acc[i][j] + bias[ng_off + tx * 8 + j];
    }
}

// ---------------- persistent GRU recurrence ----------------
// CTA owns 4 columns c0..c0+3 (z, r, g share the same 4 h-columns).
// Lane = batch, warp = K-chunk of 64. Each warp STAGES ITS OWN K-chunk
// (warp-self-contained cp.async; no cross-warp staging dependency), then each
// lane computes all 8 (z|r) columns for its batch over the warp's K-chunk;
// partials reduced via SMEM.
__global__ void __launch_bounds__(256, 1) gru_recur_kernel(
    const float* __restrict__ Abuf,
    const float* __restrict__ Whz, const float* __restrict__ Whr, const float* __restrict__ Whg,
    float* __restrict__ hcur, float* __restrict__ Hout,
    float* __restrict__ rhbuf)
{
    extern __shared__ float smf[];
    float* wA   = smf;                   // [8][512]  z cols 0-3, r cols 4-7 (k-major)
    float* wB   = wA + 8 * 512;          // [4][512]  g cols
    float* h_s  = wB + 4 * 512;          // [32][HSTRIDE]  h, reused for r*h
    float* red  = h_s + 32 * HSTRIDE;    // [8 warps][8 cols][32 b]
    float* z_s  = red + 8 * 256;         // [4][32]
    float* hcol = z_s + 128;             // [4][32]  CTA's own h columns (persistent)

    const int tid = threadIdx.x;
    const int cta = blockIdx.x;
    const int c0 = cta * 4;
    const int lane = tid & 31, kw = tid >> 5;
    const int rb = tid & 31, rc = tid >> 5;   // reduce mapping (b, col)
    const int kbase = kw * 64;

    // stage step-invariant weights into SMEM (once)
    for (int idx = tid; idx < 8 * 512; idx += 256) {
        int c = idx >> 9, k = idx & 511;
        const float* Wm = (c < 4) ? Whz : Whr;
        wA[idx] = Wm[k * 512 + c0 + (c & 3)];
    }
    for (int idx = tid; idx < 4 * 512; idx += 256) {
        int c = idx >> 9, k = idx & 511;
        wB[idx] = Whg[k * 512 + c0 + c];
    }
    if (tid < 128) hcol[tid] = hcur[rb * 512 + c0 + rc];
    __syncthreads();

    unsigned tgt = 0;

    for (int t = 0; t < SS; t++) {
        // ---- stage h: warp kw copies ONLY its K-chunk [kbase, kbase+64) ----
        // 512 float4 per warp; lanes cover 256B contiguous runs (coalesced).
#pragma unroll
        for (int it = 0; it < 16; it++) {
            int e = it * 32 + lane;            // 0..511
            int row = e >> 4, f4 = e & 15;
            cp_async16(&h_s[row * HSTRIDE + kbase + f4 * 4],
                       hcur + row * 512 + kbase + f4 * 4);
        }
        cp_commit();

        // overlap: prefetch this step's Abuf terms (reduce mapping)
        float pZR = __ldg(Abuf + (size_t)(t * 32 + rb) * 1536 +
                          (rc < 4 ? c0 + rc : 512 + c0 + rc - 4));
        float pG = 0.f;
        if (tid < 128)
            pG = __ldg(Abuf + (size_t)(t * 32 + rb) * 1536 + 1024 + c0 + rc);

        cp_wait<0>();
        __syncwarp();

        // ---- Phase A dot: 8 cols x K-chunk 64, lane = batch ----
        {
            float acc[8];
#pragma unroll
            for (int c = 0; c < 8; c++) acc[c] = 0.f;
            const float* hp = h_s + lane * HSTRIDE + kbase;
            const float* wp = wA + kbase;
#pragma unroll
            for (int k4 = 0; k4 < 16; k4++) {
                float4 h4 = *(const float4*)(hp + k4 * 4);
#pragma unroll
                for (int c = 0; c < 8; c++) {
                    float4 w4 = *(const float4*)(wp + c * 512 + k4 * 4);
                    acc[c] += h4.x * w4.x + h4.y * w4.y + h4.z * w4.z + h4.w * w4.w;
                }
            }
#pragma unroll
            for (int c = 0; c < 8; c++) red[kw * 256 + c * 32 + lane] = acc[c];
        }
        __syncthreads();

        // ---- Phase A reduce + activations ----
        {
            float s = pZR;
#pragma unroll
            for (int w = 0; w < 8; w++) s += red[w * 256 + tid];
            float sg = 1.f / (1.f + __expf(-s));
            if (rc < 4) {
                z_s[tid] = sg;                       // z for col rc, batch rb
            } else {
                float rh = sg * hcol[(rc - 4) * 32 + rb];
                __stcg(&rhbuf[rb * 512 + c0 + rc - 4], rh);
            }
        }
        grid_sync(tgt);

        // ---- stage r*h into h_s (reuse): again warp-self-contained ----
#pragma unroll
        for (int it = 0; it < 16; it++) {
            int e = it * 32 + lane;
            int row = e >> 4, f4 = e & 15;
            cp_async16(&h_s[row * HSTRIDE + kbase + f4 * 4],
                       rhbuf + row * 512 + kbase + f4 * 4);
        }
        cp_commit();
        cp_wait<0>();
        __syncwarp();

        // ---- Phase B dot: 4 g cols ----
        {
            float acc[4] = {0.f, 0.f, 0.f, 0.f};
            const float* rp = h_s + lane * HSTRIDE + kbase;
            const float* wp = wB + kbase;
#pragma unroll
            for (int k4 = 0; k4 < 16; k4++) {
                float4 h4 = *(const float4*)(rp + k4 * 4);
#pragma unroll
                for (int c = 0; c < 4; c++) {
                    float4 w4 = *(const float4*)(wp + c * 512 + k4 * 4);
                    acc[c] += h4.x * w4.x + h4.y * w4.y + h4.z * w4.z + h4.w * w4.w;
                }
            }
#pragma unroll
            for (int c = 0; c < 4; c++) red[kw * 256 + c * 32 + lane] = acc[c];
        }
        __syncthreads();

        // ---- Phase B reduce + h update ----
        if (tid < 128) {
            float s = pG;
#pragma unroll
            for (int w = 0; w < 8; w++) s += red[w * 256 + tid];
            float g = tanhf(s);
            float z = z_s[tid];
            float ho = hcol[tid];
            float hn = z * ho + (1.f - z) * g;
            hcol[tid] = hn;
            __stcg(&hcur[rb * 512 + c0 + rc], hn);
            Hout[(size_t)(t * 32 + rb) * 512 + c0 + rc] = hn;
        }
        grid_sync(tgt);
    }
}

// ---------------- small helpers ----------------
__global__ void init_h_kernel(const float* __restrict__ h0, float* __restrict__ hc) {
    int i = blockIdx.x * 256 + threadIdx.x;
    if (i < 2 * BB * HH) {
        int l = i >> 14, rem = i & 16383, b = rem >> 9, h = rem & 511;
        hc[i] = h0[b * 1024 + l * 512 + h];
    }
}

__global__ void copy_hidden_kernel(float* __restrict__ out, const float* __restrict__ hc) {
    int i = blockIdx.x * 256 + threadIdx.x;
    if (i < BB * 2 * HH) {
        int b = i >> 10, rem = i & 1023;
        int l = rem >> 9, h = rem & 511;
        out[i] = hc[l * (BB * HH) + (b << 9) + h];
    }
}

// ---------------- launch ----------------
extern "C" void kernel_launch(void* const* d_in, const int* in_sizes, int n_in,
                              void* d_out, int out_size)
{
    const float* x    = (const float*)d_in[0];
    const float* h0   = (const float*)d_in[1];
    const float* W0xz = (const float*)d_in[2];
    const float* W0hz = (const float*)d_in[3];
    const float* b0z  = (const float*)d_in[4];
    const float* W0xr = (const float*)d_in[5];
    const float* W0hr = (const float*)d_in[6];
    const float* b0r  = (const float*)d_in[7];
    const float* W0xg = (const float*)d_in[8];
    const float* W0hg = (const float*)d_in[9];
    const float* b0g  = (const float*)d_in[10];
    const float* W1xz = (const float*)d_in[11];
    const float* W1hz = (const float*)d_in[12];
    const float* b1z  = (const float*)d_in[13];
    const float* W1xr = (const float*)d_in[14];
    const float* W1hr = (const float*)d_in[15];
    const float* b1r  = (const float*)d_in[16];
    const float* W1xg = (const float*)d_in[17];
    const float* W1hg = (const float*)d_in[18];
    const float* b1g  = (const float*)d_in[19];
    const float* Wy   = (const float*)d_in[20];
    const float* by   = (const float*)d_in[21];
    float* out = (float*)d_out;

    float *Abuf, *H0, *H1, *hc, *rhb;
    cudaGetSymbolAddress((void**)&Abuf, g_Abuf);
    cudaGetSymbolAddress((void**)&H0,   g_H0);
    cudaGetSymbolAddress((void**)&H1,   g_H1);
    cudaGetSymbolAddress((void**)&hc,   g_hc);
    cudaGetSymbolAddress((void**)&rhb,  g_rhbuf);

    // smem: wA 8*512 + wB 4*512 + h_s 32*HSTRIDE + red 8*256 + z 128 + hcol 128
    const size_t smem = (size_t)(8 * 512 + 4 * 512 + 32 * HSTRIDE + 8 * 256 + 256)
                        * sizeof(float);   // ~97.5 KB
    cudaFuncSetAttribute(gru_recur_kernel,
                         cudaFuncAttributeMaxDynamicSharedMemorySize, (int)smem);

    init_h_kernel<<<128, 256>>>(h0, hc);

    dim3 gproj(512, 12);  // M=65536/128, N=1536/128

    // layer 0
    sgemm_kernel<<<gproj, 256>>>(x, 0, II, W0xz, W0xr, W0xg, b0z, b0r, b0g,
                                 512, Abuf, 0, 1536);
    reset_bar_kernel<<<1, 1>>>();
    gru_recur_kernel<<<RGRID, 256, smem>>>(Abuf, W0hz, W0hr, W0hg,
                                           hc, H0, rhb);

    // layer 1
    sgemm_kernel<<<gproj, 256>>>(H0, 1, HH, W1xz, W1xr, W1xg, b1z, b1r, b1g,
                                 512, Abuf, 0, 1536);
    reset_bar_kernel<<<1, 1>>>();
    gru_recur_kernel<<<RGRID, 256, smem>>>(Abuf, W1hz, W1hr, W1hg,
                                           hc + BB * HH, H1, rhb);

    // output head
    dim3 ghead(512, 1);
    sgemm_kernel<<<ghead, 256>>>(H1, 1, HH, Wy, Wy, Wy, by, by, by,
                                 128, out, 1, 0);

    if (out_size >= BB * SS * OO + BB * 2 * HH) {
        copy_hidden_kernel<<<128, 256>>>(out + BB * SS * OO, hc);
    }
}